// round 6
// baseline (speedup 1.0000x reference)
#include <cuda_runtime.h>
#include <cuda_bf16.h>
#include <cstdint>

constexpr int Nn = 16384, Ee = 524288;

// ---- scratch (device globals; allocs forbidden) ----
__device__ __nv_bfloat16 g_Abf[268435456];   // A in bf16, 512 MB
__device__ __nv_bfloat16 g_Tbf[64 * Nn];     // (X@W)^T in bf16, [64][Nn] K-major
__device__ float g_H1[Nn * 64];
__device__ float g_H2[Nn * 64];
__device__ float g_U[Nn * 256];
__device__ float g_V[Nn * 256];

// ---- A fp32 -> bf16 (streaming, vectorized) ----
__global__ void __launch_bounds__(256) cvt_A(const float4* __restrict__ A, uint2* __restrict__ O) {
    const size_t n4 = (size_t)Nn * Nn / 4;
    for (size_t i = (size_t)blockIdx.x * 256 + threadIdx.x; i < n4; i += (size_t)gridDim.x * 256) {
        float4 v = __ldg(A + i);
        __nv_bfloat162 lo = __floats2bfloat162_rn(v.x, v.y);
        __nv_bfloat162 hi = __floats2bfloat162_rn(v.z, v.w);
        uint2 o;
        o.x = *reinterpret_cast<uint32_t*>(&lo);
        o.y = *reinterpret_cast<uint32_t*>(&hi);
        O[i] = o;
    }
}

// ---- Tbf[n][r] = bf16( sum_k X[r][k] * W[k][n] ), K in {128, 64}, 64 outputs ----
template <int K>
__global__ void __launch_bounds__(256)
k_xw(const float* __restrict__ X, const float* __restrict__ W, __nv_bfloat16* __restrict__ Tbf) {
    __shared__ float Ws[K * 64];
    const int tid = threadIdx.x;
    for (int i = tid; i < K * 64; i += 256) Ws[i] = W[i];
    __syncthreads();
    const int r = blockIdx.x * 256 + tid;
    float acc[64];
    #pragma unroll
    for (int n = 0; n < 64; n++) acc[n] = 0.f;
    const float4* xr = (const float4*)(X + (size_t)r * K);
    #pragma unroll 4
    for (int k4 = 0; k4 < K / 4; k4++) {
        float4 xv = __ldg(xr + k4);
        float xs[4] = {xv.x, xv.y, xv.z, xv.w};
        #pragma unroll
        for (int u = 0; u < 4; u++) {
            const float* wk = &Ws[(k4 * 4 + u) * 64];
            #pragma unroll
            for (int n = 0; n < 64; n++) acc[n] = fmaf(xs[u], wk[n], acc[n]);
        }
    }
    #pragma unroll
    for (int n = 0; n < 64; n++) Tbf[(size_t)n * Nn + r] = __float2bfloat16(acc[n]);
}

// ---- bf16 mma.sync GEMM: H[16384,64] = sigmoid(Abf[16384,16384] @ Tbf^T + bias) ----
constexpr int MT = 128, KC = 64, ST = 4, NIT = Nn / KC;
constexpr int AS = 72;                     // smem row stride (bf16 elems): 64 + 8 pad -> 144 B
constexpr int A_STG = 128 * AS;            // elems per A stage
constexpr int B_STG = 64 * AS;
constexpr int STG_E = A_STG + B_STG;       // 13824 elems = 27648 B per stage
constexpr int SMEM_DYN = ST * STG_E * 2;   // 110592 B

__device__ __forceinline__ void ld_stage(const __nv_bfloat16* __restrict__ A,
                                         const __nv_bfloat16* __restrict__ B,
                                         __nv_bfloat16* sm, int m0, int it, int tid) {
    const int k0 = it * KC;
    uint32_t sbu = (uint32_t)__cvta_generic_to_shared(sm + (it % ST) * STG_E);
    #pragma unroll
    for (int i = 0; i < 6; i++) {
        int f = i * 256 + tid;                       // 16B chunks: A 1024, B 512
        const __nv_bfloat16* src;
        uint32_t dst;
        if (f < 1024) {
            int r = f >> 3, c = f & 7;
            src = A + (size_t)(m0 + r) * Nn + k0 + c * 8;
            dst = sbu + (uint32_t)(r * AS + c * 8) * 2;
        } else {
            int f2 = f - 1024;
            int n = f2 >> 3, c = f2 & 7;
            src = B + (size_t)n * Nn + k0 + c * 8;
            dst = sbu + (uint32_t)(A_STG + n * AS + c * 8) * 2;
        }
        asm volatile("cp.async.cg.shared.global [%0], [%1], 16;" :: "r"(dst), "l"(src) : "memory");
    }
}

__global__ void __launch_bounds__(256, 1)
gemm_bf16_sig(const __nv_bfloat16* __restrict__ A, const __nv_bfloat16* __restrict__ B,
              const float* __restrict__ bias, float* __restrict__ H) {
    extern __shared__ __nv_bfloat16 sm[];
    const int tid = threadIdx.x, wid = tid >> 5, lane = tid & 31;
    const int wm = wid >> 1, wn = wid & 1;           // warps 4(M) x 2(N)
    const int ln4 = lane >> 2, lm4 = lane & 3;
    const int m0 = blockIdx.x * MT;

    float c[2][4][4];
    #pragma unroll
    for (int a = 0; a < 2; a++)
        #pragma unroll
        for (int b = 0; b < 4; b++)
            #pragma unroll
            for (int q = 0; q < 4; q++) c[a][b][q] = 0.f;

    #pragma unroll
    for (int s = 0; s < ST - 1; s++) {
        ld_stage(A, B, sm, m0, s, tid);
        asm volatile("cp.async.commit_group;" ::: "memory");
    }

    for (int it = 0; it < NIT; it++) {
        asm volatile("cp.async.wait_group 2;" ::: "memory");
        __syncthreads();
        const __nv_bfloat16* Asm = sm + (it % ST) * STG_E;
        const __nv_bfloat16* Bsm = Asm + A_STG;
        #pragma unroll
        for (int ks = 0; ks < 4; ks++) {
            const int kb = ks * 16 + lm4 * 2;
            uint32_t a[2][4], bf[4][2];
            #pragma unroll
            for (int mt = 0; mt < 2; mt++) {
                const __nv_bfloat16* ap = Asm + (wm * 32 + mt * 16 + ln4) * AS + kb;
                a[mt][0] = *(const uint32_t*)ap;
                a[mt][1] = *(const uint32_t*)(ap + 8 * AS);
                a[mt][2] = *(const uint32_t*)(ap + 8);
                a[mt][3] = *(const uint32_t*)(ap + 8 * AS + 8);
            }
            #pragma unroll
            for (int nt = 0; nt < 4; nt++) {
                const __nv_bfloat16* bp = Bsm + (wn * 32 + nt * 8 + ln4) * AS + kb;
                bf[nt][0] = *(const uint32_t*)bp;
                bf[nt][1] = *(const uint32_t*)(bp + 8);
            }
            #pragma unroll
            for (int mt = 0; mt < 2; mt++)
                #pragma unroll
                for (int nt = 0; nt < 4; nt++)
                    asm volatile(
                        "mma.sync.aligned.m16n8k16.row.col.f32.bf16.bf16.f32 "
                        "{%0,%1,%2,%3}, {%4,%5,%6,%7}, {%8,%9}, {%0,%1,%2,%3};"
                        : "+f"(c[mt][nt][0]), "+f"(c[mt][nt][1]),
                          "+f"(c[mt][nt][2]), "+f"(c[mt][nt][3])
                        : "r"(a[mt][0]), "r"(a[mt][1]), "r"(a[mt][2]), "r"(a[mt][3]),
                          "r"(bf[nt][0]), "r"(bf[nt][1]));
        }
        if (it + ST - 1 < NIT) ld_stage(A, B, sm, m0, it + ST - 1, tid);
        asm volatile("cp.async.commit_group;" ::: "memory");
    }

    // epilogue: bias + sigmoid, fp32 out
    #pragma unroll
    for (int mt = 0; mt < 2; mt++)
        #pragma unroll
        for (int nt = 0; nt < 4; nt++) {
            const int col = wn * 32 + nt * 8 + lm4 * 2;
            const float b0 = __ldg(bias + col), b1 = __ldg(bias + col + 1);
            #pragma unroll
            for (int h = 0; h < 2; h++) {
                const int row = m0 + wm * 32 + mt * 16 + ln4 + h * 8;
                const float x0 = c[mt][nt][2 * h] + b0, x1 = c[mt][nt][2 * h + 1] + b1;
                *(float2*)(H + (size_t)row * 64 + col) =
                    make_float2(1.f / (1.f + __expf(-x0)), 1.f / (1.f + __expf(-x1)));
            }
        }
}

// ---- u = H2 @ Wd[0:64], v = H2 @ Wd[64:128] ----
__global__ void __launch_bounds__(256)
k4_uv(const float* __restrict__ H2, const float* __restrict__ Wd,
      float* __restrict__ U, float* __restrict__ V) {
    __shared__ float Hs[32 * 65];
    const int tid = threadIdx.x, r0 = blockIdx.x * 32;
    for (int i = tid; i < 32 * 64; i += 256)
        Hs[(i >> 6) * 65 + (i & 63)] = H2[(size_t)(r0 + (i >> 6)) * 64 + (i & 63)];
    __syncthreads();
    const int rl = tid >> 3, c0 = (tid & 7) * 32;
    float au[32], av[32];
    #pragma unroll
    for (int q = 0; q < 32; q++) { au[q] = 0.f; av[q] = 0.f; }
    for (int j = 0; j < 64; j++) {
        const float h = Hs[rl * 65 + j];
        const float4* wu = (const float4*)(Wd + (size_t)j * 256 + c0);
        const float4* wv = (const float4*)(Wd + (size_t)(64 + j) * 256 + c0);
        #pragma unroll
        for (int q = 0; q < 8; q++) {
            float4 a = __ldg(wu + q);
            au[4*q+0] = fmaf(h, a.x, au[4*q+0]); au[4*q+1] = fmaf(h, a.y, au[4*q+1]);
            au[4*q+2] = fmaf(h, a.z, au[4*q+2]); au[4*q+3] = fmaf(h, a.w, au[4*q+3]);
            float4 b = __ldg(wv + q);
            av[4*q+0] = fmaf(h, b.x, av[4*q+0]); av[4*q+1] = fmaf(h, b.y, av[4*q+1]);
            av[4*q+2] = fmaf(h, b.z, av[4*q+2]); av[4*q+3] = fmaf(h, b.w, av[4*q+3]);
        }
    }
    float4* uo = (float4*)(U + (size_t)(r0 + rl) * 256 + c0);
    float4* vo = (float4*)(V + (size_t)(r0 + rl) * 256 + c0);
    #pragma unroll
    for (int q = 0; q < 8; q++) {
        uo[q] = make_float4(au[4*q], au[4*q+1], au[4*q+2], au[4*q+3]);
        vo[q] = make_float4(av[4*q], av[4*q+1], av[4*q+2], av[4*q+3]);
    }
}

// ---- per-edge: softmax(relu(u[i]+v[j]+bd) @ Wo + bo) * mask  (1 warp / edge) ----
__global__ void __launch_bounds__(256)
edge_k(const int* __restrict__ eg, const int* __restrict__ msk,
       const float* __restrict__ U, const float* __restrict__ V,
       const float* __restrict__ bd, const float* __restrict__ Wo,
       const float* __restrict__ bo, float* __restrict__ out) {
    const int e = blockIdx.x * 8 + (threadIdx.x >> 5);
    const int lane = threadIdx.x & 31;
    const int i = __ldg(&eg[2 * e]), j = __ldg(&eg[2 * e + 1]);
    const float4* up = (const float4*)(U + (size_t)i * 256) + lane * 2;
    const float4* vp = (const float4*)(V + (size_t)j * 256) + lane * 2;
    const float4* bp = (const float4*)bd + lane * 2;
    float z0 = 0.f, z1 = 0.f;
    #pragma unroll
    for (int q = 0; q < 2; q++) {
        float4 u = __ldg(up + q), v = __ldg(vp + q), b = __ldg(bp + q);
        const int cc = lane * 8 + q * 4;
        float s;
        s = fmaxf(u.x + v.x + b.x, 0.f); z0 = fmaf(s, __ldg(&Wo[2*cc+0]), z0); z1 = fmaf(s, __ldg(&Wo[2*cc+1]), z1);
        s = fmaxf(u.y + v.y + b.y, 0.f); z0 = fmaf(s, __ldg(&Wo[2*cc+2]), z0); z1 = fmaf(s, __ldg(&Wo[2*cc+3]), z1);
        s = fmaxf(u.z + v.z + b.z, 0.f); z0 = fmaf(s, __ldg(&Wo[2*cc+4]), z0); z1 = fmaf(s, __ldg(&Wo[2*cc+5]), z1);
        s = fmaxf(u.w + v.w + b.w, 0.f); z0 = fmaf(s, __ldg(&Wo[2*cc+6]), z0); z1 = fmaf(s, __ldg(&Wo[2*cc+7]), z1);
    }
    #pragma unroll
    for (int o = 16; o; o >>= 1) {
        z0 += __shfl_xor_sync(0xFFFFFFFFu, z0, o);
        z1 += __shfl_xor_sync(0xFFFFFFFFu, z1, o);
    }
    if (lane == 0) {
        z0 += __ldg(&bo[0]); z1 += __ldg(&bo[1]);
        const float m = fmaxf(z0, z1);
        const float e0 = __expf(z0 - m), e1 = __expf(z1 - m);
        const float inv = 1.f / (e0 + e1);
        const float fm = (float)__ldg(&msk[e]);
        ((float2*)out)[e] = make_float2(e0 * inv * fm, e1 * inv * fm);
    }
}

extern "C" void kernel_launch(void* const* d_in, const int* in_sizes, int n_in,
                              void* d_out, int out_size) {
    const float* X  = (const float*)d_in[0];
    const float* A  = (const float*)d_in[1];
    const int*   eg = (const int*)d_in[2];
    const int*   mk = (const int*)d_in[3];
    const float* W1 = (const float*)d_in[4];
    const float* b1 = (const float*)d_in[5];
    const float* W2 = (const float*)d_in[6];
    const float* b2 = (const float*)d_in[7];
    const float* Wd = (const float*)d_in[8];
    const float* bd = (const float*)d_in[9];
    const float* Wo = (const float*)d_in[10];
    const float* bo = (const float*)d_in[11];
    float* out = (float*)d_out;

    __nv_bfloat16 *Abf, *Tbf;
    float *H1, *H2, *U, *V;
    cudaGetSymbolAddress((void**)&Abf, g_Abf);
    cudaGetSymbolAddress((void**)&Tbf, g_Tbf);
    cudaGetSymbolAddress((void**)&H1, g_H1);
    cudaGetSymbolAddress((void**)&H2, g_H2);
    cudaGetSymbolAddress((void**)&U,  g_U);
    cudaGetSymbolAddress((void**)&V,  g_V);

    cudaFuncSetAttribute(gemm_bf16_sig, cudaFuncAttributeMaxDynamicSharedMemorySize, SMEM_DYN);

    cvt_A<<<2048, 256>>>((const float4*)A, (uint2*)Abf);
    k_xw<128><<<Nn / 256, 256>>>(X, W1, Tbf);
    gemm_bf16_sig<<<Nn / MT, 256, SMEM_DYN>>>(Abf, Tbf, b1, H1);
    k_xw<64><<<Nn / 256, 256>>>(H1, W2, Tbf);
    gemm_bf16_sig<<<Nn / MT, 256, SMEM_DYN>>>(Abf, Tbf, b2, H2);
    k4_uv<<<Nn / 32, 256>>>(H2, Wd, U, V);
    edge_k<<<Ee / 8, 256>>>(eg, mk, U, V, bd, Wo, bo, out);
}

// round 11
// speedup vs baseline: 1.0967x; 1.0967x over previous
#include <cuda_runtime.h>
#include <cuda_bf16.h>
#include <cstdint>

constexpr int Nn = 16384, Ee = 524288;

// ---- scratch (device globals; allocs forbidden) ----
__device__ __nv_bfloat16 g_Tbf[64 * Nn];     // (X@W)^T in bf16, [64][Nn] K-major
__device__ float g_H1[Nn * 64];
__device__ float g_H2[Nn * 64];
__device__ float g_U[Nn * 256];
__device__ float g_V[Nn * 256];

// ---- Tbf[n][r] = bf16( sum_k X[r][k] * W[k][n] ), K in {128, 64}, 64 outputs ----
template <int K>
__global__ void __launch_bounds__(256)
k_xw(const float* __restrict__ X, const float* __restrict__ W, __nv_bfloat16* __restrict__ Tbf) {
    __shared__ float Ws[K * 64];
    const int tid = threadIdx.x;
    for (int i = tid; i < K * 64; i += 256) Ws[i] = W[i];
    __syncthreads();
    const int r = blockIdx.x * 256 + tid;
    float acc[64];
    #pragma unroll
    for (int n = 0; n < 64; n++) acc[n] = 0.f;
    const float4* xr = (const float4*)(X + (size_t)r * K);
    #pragma unroll 4
    for (int k4 = 0; k4 < K / 4; k4++) {
        float4 xv = __ldg(xr + k4);
        float xs[4] = {xv.x, xv.y, xv.z, xv.w};
        #pragma unroll
        for (int u = 0; u < 4; u++) {
            const float* wk = &Ws[(k4 * 4 + u) * 64];
            #pragma unroll
            for (int n = 0; n < 64; n++) acc[n] = fmaf(xs[u], wk[n], acc[n]);
        }
    }
    #pragma unroll
    for (int n = 0; n < 64; n++) Tbf[(size_t)n * Nn + r] = __float2bfloat16(acc[n]);
}

// ---- GEMM: H[16384,64] = sigmoid(A_fp32[16384,16384] @ Tbf^T + bias) ----
// A streamed as fp32 via cp.async, converted to bf16 in-register for mma.sync.
constexpr int MT = 128, KC = 64, ST = 4, NIT = Nn / KC;
constexpr int ASf = 72;                       // A smem row stride (floats) -> 288 B
constexpr int BSe = 72;                       // B smem row stride (bf16)   -> 144 B
constexpr int A_BYTES = 128 * ASf * 4;        // 36864
constexpr int B_BYTES = 64 * BSe * 2;         // 9216
constexpr int STG_B = A_BYTES + B_BYTES;      // 46080
constexpr int SMEM_DYN = ST * STG_B;          // 184320

__device__ __forceinline__ uint32_t cvt2(float2 p) {
    uint32_t r;
    asm("cvt.rn.bf16x2.f32 %0, %1, %2;" : "=r"(r) : "f"(p.y), "f"(p.x));
    return r;
}

__device__ __forceinline__ void ld_stage(const float* __restrict__ Af,
                                         const __nv_bfloat16* __restrict__ Bt,
                                         char* sm, int m0, int it, int tid) {
    const int k0 = it * KC;
    const uint32_t sb = (uint32_t)__cvta_generic_to_shared(sm + (it % ST) * STG_B);
    #pragma unroll
    for (int i = 0; i < 10; i++) {
        const int f = i * 256 + tid;          // 16B chunks: A 2048, B 512
        uint32_t dst;
        const void* src;
        if (f < 2048) {
            const int r = f >> 4, c = f & 15;
            src = Af + (size_t)(m0 + r) * Nn + k0 + c * 4;
            dst = sb + (uint32_t)(r * 288 + c * 16);
        } else {
            const int f2 = f - 2048;
            const int n = f2 >> 3, c = f2 & 7;
            src = Bt + (size_t)n * Nn + k0 + c * 8;
            dst = sb + (uint32_t)(A_BYTES + n * 144 + c * 16);
        }
        asm volatile("cp.async.cg.shared.global [%0], [%1], 16;" :: "r"(dst), "l"(src) : "memory");
    }
}

__global__ void __launch_bounds__(256, 1)
gemm_f32a_sig(const float* __restrict__ Af, const __nv_bfloat16* __restrict__ Bt,
              const float* __restrict__ bias, float* __restrict__ H) {
    extern __shared__ char smem[];
    const int tid = threadIdx.x, wid = tid >> 5, lane = tid & 31;
    const int wm = wid >> 1, wn = wid & 1;    // warps 4(M) x 2(N)
    const int ln4 = lane >> 2, lm4 = lane & 3;
    const int m0 = blockIdx.x * MT;

    float c[2][4][4];
    #pragma unroll
    for (int a = 0; a < 2; a++)
        #pragma unroll
        for (int b = 0; b < 4; b++)
            #pragma unroll
            for (int q = 0; q < 4; q++) c[a][b][q] = 0.f;

    #pragma unroll
    for (int s = 0; s < ST - 1; s++) {
        ld_stage(Af, Bt, smem, m0, s, tid);
        asm volatile("cp.async.commit_group;" ::: "memory");
    }

    for (int it = 0; it < NIT; it++) {
        asm volatile("cp.async.wait_group 2;" ::: "memory");
        __syncthreads();
        const float* Asm = (const float*)(smem + (it % ST) * STG_B);
        const __nv_bfloat16* Bsm = (const __nv_bfloat16*)(smem + (it % ST) * STG_B + A_BYTES);
        #pragma unroll
        for (int ks = 0; ks < 4; ks++) {
            const int kb = ks * 16 + lm4 * 2;
            uint32_t a[2][4], bf[4][2];
            #pragma unroll
            for (int mt = 0; mt < 2; mt++) {
                const float* ap = Asm + (wm * 32 + mt * 16 + ln4) * ASf + kb;
                a[mt][0] = cvt2(*(const float2*)ap);
                a[mt][1] = cvt2(*(const float2*)(ap + 8 * ASf));
                a[mt][2] = cvt2(*(const float2*)(ap + 8));
                a[mt][3] = cvt2(*(const float2*)(ap + 8 * ASf + 8));
            }
            #pragma unroll
            for (int nt = 0; nt < 4; nt++) {
                const __nv_bfloat16* bp = Bsm + (wn * 32 + nt * 8 + ln4) * BSe + kb;
                bf[nt][0] = *(const uint32_t*)bp;
                bf[nt][1] = *(const uint32_t*)(bp + 8);
            }
            #pragma unroll
            for (int mt = 0; mt < 2; mt++)
                #pragma unroll
                for (int nt = 0; nt < 4; nt++)
                    asm volatile(
                        "mma.sync.aligned.m16n8k16.row.col.f32.bf16.bf16.f32 "
                        "{%0,%1,%2,%3}, {%4,%5,%6,%7}, {%8,%9}, {%0,%1,%2,%3};"
                        : "+f"(c[mt][nt][0]), "+f"(c[mt][nt][1]),
                          "+f"(c[mt][nt][2]), "+f"(c[mt][nt][3])
                        : "r"(a[mt][0]), "r"(a[mt][1]), "r"(a[mt][2]), "r"(a[mt][3]),
                          "r"(bf[nt][0]), "r"(bf[nt][1]));
        }
        if (it + ST - 1 < NIT) ld_stage(Af, Bt, smem, m0, it + ST - 1, tid);
        asm volatile("cp.async.commit_group;" ::: "memory");
    }

    // epilogue: bias + sigmoid, fp32 out
    #pragma unroll
    for (int mt = 0; mt < 2; mt++)
        #pragma unroll
        for (int nt = 0; nt < 4; nt++) {
            const int col = wn * 32 + nt * 8 + lm4 * 2;
            const float b0 = __ldg(bias + col), b1 = __ldg(bias + col + 1);
            #pragma unroll
            for (int h = 0; h < 2; h++) {
                const int row = m0 + wm * 32 + mt * 16 + ln4 + h * 8;
                const float x0 = c[mt][nt][2 * h] + b0, x1 = c[mt][nt][2 * h + 1] + b1;
                *(float2*)(H + (size_t)row * 64 + col) =
                    make_float2(1.f / (1.f + __expf(-x0)), 1.f / (1.f + __expf(-x1)));
            }
        }
}

// ---- u = H2 @ Wd[0:64], v = H2 @ Wd[64:128] ----
__global__ void __launch_bounds__(256)
k4_uv(const float* __restrict__ H2, const float* __restrict__ Wd,
      float* __restrict__ U, float* __restrict__ V) {
    __shared__ float Hs[32 * 65];
    const int tid = threadIdx.x, r0 = blockIdx.x * 32;
    for (int i = tid; i < 32 * 64; i += 256)
        Hs[(i >> 6) * 65 + (i & 63)] = H2[(size_t)(r0 + (i >> 6)) * 64 + (i & 63)];
    __syncthreads();
    const int rl = tid >> 3, c0 = (tid & 7) * 32;
    float au[32], av[32];
    #pragma unroll
    for (int q = 0; q < 32; q++) { au[q] = 0.f; av[q] = 0.f; }
    for (int j = 0; j < 64; j++) {
        const float h = Hs[rl * 65 + j];
        const float4* wu = (const float4*)(Wd + (size_t)j * 256 + c0);
        const float4* wv = (const float4*)(Wd + (size_t)(64 + j) * 256 + c0);
        #pragma unroll
        for (int q = 0; q < 8; q++) {
            float4 a = __ldg(wu + q);
            au[4*q+0] = fmaf(h, a.x, au[4*q+0]); au[4*q+1] = fmaf(h, a.y, au[4*q+1]);
            au[4*q+2] = fmaf(h, a.z, au[4*q+2]); au[4*q+3] = fmaf(h, a.w, au[4*q+3]);
            float4 b = __ldg(wv + q);
            av[4*q+0] = fmaf(h, b.x, av[4*q+0]); av[4*q+1] = fmaf(h, b.y, av[4*q+1]);
            av[4*q+2] = fmaf(h, b.z, av[4*q+2]); av[4*q+3] = fmaf(h, b.w, av[4*q+3]);
        }
    }
    float4* uo = (float4*)(U + (size_t)(r0 + rl) * 256 + c0);
    float4* vo = (float4*)(V + (size_t)(r0 + rl) * 256 + c0);
    #pragma unroll
    for (int q = 0; q < 8; q++) {
        uo[q] = make_float4(au[4*q], au[4*q+1], au[4*q+2], au[4*q+3]);
        vo[q] = make_float4(av[4*q], av[4*q+1], av[4*q+2], av[4*q+3]);
    }
}

// ---- per-edge: softmax(relu(u[i]+v[j]+bd) @ Wo + bo) * mask  (1 warp / edge) ----
__global__ void __launch_bounds__(256)
edge_k(const int* __restrict__ eg, const int* __restrict__ msk,
       const float* __restrict__ U, const float* __restrict__ V,
       const float* __restrict__ bd, const float* __restrict__ Wo,
       const float* __restrict__ bo, float* __restrict__ out) {
    const int e = blockIdx.x * 8 + (threadIdx.x >> 5);
    const int lane = threadIdx.x & 31;
    const int i = __ldg(&eg[2 * e]), j = __ldg(&eg[2 * e + 1]);
    const float4* up = (const float4*)(U + (size_t)i * 256) + lane * 2;
    const float4* vp = (const float4*)(V + (size_t)j * 256) + lane * 2;
    const float4* bp = (const float4*)bd + lane * 2;
    float z0 = 0.f, z1 = 0.f;
    #pragma unroll
    for (int q = 0; q < 2; q++) {
        float4 u = __ldg(up + q), v = __ldg(vp + q), b = __ldg(bp + q);
        const int cc = lane * 8 + q * 4;
        float s;
        s = fmaxf(u.x + v.x + b.x, 0.f); z0 = fmaf(s, __ldg(&Wo[2*cc+0]), z0); z1 = fmaf(s, __ldg(&Wo[2*cc+1]), z1);
        s = fmaxf(u.y + v.y + b.y, 0.f); z0 = fmaf(s, __ldg(&Wo[2*cc+2]), z0); z1 = fmaf(s, __ldg(&Wo[2*cc+3]), z1);
        s = fmaxf(u.z + v.z + b.z, 0.f); z0 = fmaf(s, __ldg(&Wo[2*cc+4]), z0); z1 = fmaf(s, __ldg(&Wo[2*cc+5]), z1);
        s = fmaxf(u.w + v.w + b.w, 0.f); z0 = fmaf(s, __ldg(&Wo[2*cc+6]), z0); z1 = fmaf(s, __ldg(&Wo[2*cc+7]), z1);
    }
    #pragma unroll
    for (int o = 16; o; o >>= 1) {
        z0 += __shfl_xor_sync(0xFFFFFFFFu, z0, o);
        z1 += __shfl_xor_sync(0xFFFFFFFFu, z1, o);
    }
    if (lane == 0) {
        z0 += __ldg(&bo[0]); z1 += __ldg(&bo[1]);
        const float m = fmaxf(z0, z1);
        const float e0 = __expf(z0 - m), e1 = __expf(z1 - m);
        const float inv = 1.f / (e0 + e1);
        const float fm = (float)__ldg(&msk[e]);
        ((float2*)out)[e] = make_float2(e0 * inv * fm, e1 * inv * fm);
    }
}

extern "C" void kernel_launch(void* const* d_in, const int* in_sizes, int n_in,
                              void* d_out, int out_size) {
    const float* X  = (const float*)d_in[0];
    const float* A  = (const float*)d_in[1];
    const int*   eg = (const int*)d_in[2];
    const int*   mk = (const int*)d_in[3];
    const float* W1 = (const float*)d_in[4];
    const float* b1 = (const float*)d_in[5];
    const float* W2 = (const float*)d_in[6];
    const float* b2 = (const float*)d_in[7];
    const float* Wd = (const float*)d_in[8];
    const float* bd = (const float*)d_in[9];
    const float* Wo = (const float*)d_in[10];
    const float* bo = (const float*)d_in[11];
    float* out = (float*)d_out;

    __nv_bfloat16 *Tbf;
    float *H1, *H2, *U, *V;
    cudaGetSymbolAddress((void**)&Tbf, g_Tbf);
    cudaGetSymbolAddress((void**)&H1, g_H1);
    cudaGetSymbolAddress((void**)&H2, g_H2);
    cudaGetSymbolAddress((void**)&U,  g_U);
    cudaGetSymbolAddress((void**)&V,  g_V);

    cudaFuncSetAttribute(gemm_f32a_sig, cudaFuncAttributeMaxDynamicSharedMemorySize, SMEM_DYN);

    k_xw<128><<<Nn / 256, 256>>>(X, W1, Tbf);
    gemm_f32a_sig<<<Nn / MT, 256, SMEM_DYN>>>(A, Tbf, b1, H1);
    k_xw<64><<<Nn / 256, 256>>>(H1, W2, Tbf);
    gemm_f32a_sig<<<Nn / MT, 256, SMEM_DYN>>>(A, Tbf, b2, H2);
    k4_uv<<<Nn / 32, 256>>>(H2, Wd, U, V);
    edge_k<<<Ee / 8, 256>>>(eg, mk, U, V, bd, Wo, bo, out);
}